// round 12
// baseline (speedup 1.0000x reference)
#include <cuda_runtime.h>
#include <cuda_fp16.h>
#include <cstdint>

// ---------------------------------------------------------------------------
// FactorizedLayer on GB300 (sm_103a) — R12: main CTA 128x128 (64x64 warp tiles)
// out[b,h] = 0.5*sum_l[(x.beta_hl)^2 - (x^2.beta_hl^2)] + x.W_h + b_h
// main: S ~= Xh @ Bh^T (single fp16 product; calibrated rel_err ~3e-4).
//       CTA 128x128 fixes the LDSM-crossbar ratio that held N=64 main ~15%
//       above its MMA-count floor. A operand read from g_Aa hi panel (no g_Xh).
// aux (fp16 K=1024, f32 acc): out = [Xh|X^2].[W|-0.5G]^T + bias  (proven)
// ---------------------------------------------------------------------------

#define DB 4096
#define DN 512
#define DH 1024
#define DL 8
#define RM (DH*DL)

__device__ __align__(16) __half g_Bh[(size_t)RM * 512];    // beta hi digit
__device__ __align__(16) __half g_Aa[(size_t)DB * 1024];   // [Xh512|X2 512]
__device__ __align__(16) __half g_Ba[(size_t)DH * 1024];   // [Wh512|G512]

// ------------------------------- prep kernels ------------------------------

__global__ void prep_A(const float* __restrict__ x) {
    int i = blockIdx.x * 256 + threadIdx.x;          // over 4096*512
    int m = i >> 9, n = i & 511;
    float v = x[i];
    size_t ba = (size_t)m * 1024;
    g_Aa[ba + n] = __float2half(v);
    g_Aa[ba + 512 + n] = __float2half(v * v);
}

__global__ void prep_Bh(const float* __restrict__ beta) {
    int i = blockIdx.x * 256 + threadIdx.x;          // over (8192*512)/4 float4s
    float4 v = ((const float4*)beta)[i];
    __half2* dst = (__half2*)g_Bh;
    dst[i * 2 + 0] = __floats2half2_rn(v.x, v.y);
    dst[i * 2 + 1] = __floats2half2_rn(v.z, v.w);
}

__global__ void prep_Ba(const float* __restrict__ beta, const float* __restrict__ W) {
    int i = blockIdx.x * 256 + threadIdx.x;          // over 1024*512
    int hh = i >> 9, n = i & 511;
    float w = W[i];
    const float* bp = beta + (size_t)hh * (DL * DN) + n;
    float g = 0.f;
#pragma unroll
    for (int l = 0; l < DL; l++) { float t = bp[l * DN]; g += t * t; }
    g *= -0.5f;
    size_t b = (size_t)hh * 1024;
    g_Ba[b + n] = __float2half(w);
    g_Ba[b + 512 + n] = __float2half(g);
}

// ------------------------------- common -----------------------------------

__device__ __forceinline__ uint32_t swz(uint32_t o) { return o ^ ((o >> 3) & 0x70); }

#define LDSM_X4(r, a)                                                           \
    asm volatile("ldmatrix.sync.aligned.m8n8.x4.shared.b16 {%0,%1,%2,%3}, [%4];"\
        : "=r"((r)[0]), "=r"((r)[1]), "=r"((r)[2]), "=r"((r)[3]) : "r"(a))

#define MMA16816F(c, a, b0, b1)                                                 \
    asm volatile("mma.sync.aligned.m16n8k16.row.col.f32.f16.f16.f32 "           \
        "{%0,%1,%2,%3}, {%4,%5,%6,%7}, {%8,%9}, {%0,%1,%2,%3};"                 \
        : "+f"((c)[0]), "+f"((c)[1]), "+f"((c)[2]), "+f"((c)[3])                 \
        : "r"((a)[0]), "r"((a)[1]), "r"((a)[2]), "r"((a)[3]), "r"(b0), "r"(b1))

// ------------------------------- main GEMM ---------------------------------
// CTA 128(M) x 128(N), 4 warps of 64x64. 8 stages of one k64 chunk.
// A from g_Aa hi panel (row stride 1024, cols 0..511), B from g_Bh (stride 512).

constexpr int TILEB = 16384;   // 128 rows x 128B per operand per stage
constexpr int MSTAGES = 3;
constexpr int SMEM_GEMM = MSTAGES * TILEB * 2;   // 98304 -> 2 CTA/SM

__global__ void __launch_bounds__(128, 2)
fm_main(const __half* __restrict__ gA, const __half* __restrict__ gB,
        float* __restrict__ out)
{
    extern __shared__ __align__(128) char smem[];
    const uint32_t sb = (uint32_t)__cvta_generic_to_shared(smem);
    const int tid = threadIdx.x, lane = tid & 31, wid = tid >> 5;
    const int cm = blockIdx.y * 128, cn = blockIdx.x * 128;
    const int wm = (wid & 1) * 64, wn = (wid >> 1) * 64;
    constexpr int KT = 8;

    const int lrow = tid >> 3;          // 0..15
    const int lchunk = tid & 7;
    const __half* gArow = gA + (size_t)(cm + lrow) * 1024 + lchunk * 8;  // hi panel
    const __half* gBrow = gB + (size_t)(cn + lrow) * 512 + lchunk * 8;

    const int a_row = wm + (lane & 15);
    const int a_ko  = ((lane >> 4) & 1) * 16;
    const int b_mi  = lane >> 3;
    const int b_row = wn + ((b_mi >> 1) & 1) * 8 + (lane & 7);
    const int b_ko  = (b_mi & 1) * 16;

    float acc[4][8][4];
#pragma unroll
    for (int i = 0; i < 4; i++)
#pragma unroll
        for (int j = 0; j < 8; j++)
#pragma unroll
            for (int q = 0; q < 4; q++) acc[i][j][q] = 0.f;

    auto load_stage = [&](int s, int kt) {
        const uint32_t sa = sb + s * TILEB;
        const uint32_t sB = sb + MSTAGES * TILEB + s * TILEB;
        const int koff = kt * 64;
#pragma unroll
        for (int i = 0; i < 8; i++) {
            uint32_t off = swz((lrow + i * 16) * 128 + lchunk * 16);
            const void* ga = gArow + (size_t)(i * 16) * 1024 + koff;
            asm volatile("cp.async.cg.shared.global [%0], [%1], 16;" :: "r"(sa + off), "l"(ga));
            const void* gb = gBrow + (size_t)(i * 16) * 512 + koff;
            asm volatile("cp.async.cg.shared.global [%0], [%1], 16;" :: "r"(sB + off), "l"(gb));
        }
    };

    auto compute = [&](int s) {
        const uint32_t sa = sb + s * TILEB;
        const uint32_t sB = sb + MSTAGES * TILEB + s * TILEB;
#pragma unroll
        for (int ks = 0; ks < 4; ks++) {
            uint32_t a[4][4];
#pragma unroll
            for (int mt = 0; mt < 4; mt++)
                LDSM_X4(a[mt], sa + swz((a_row + mt * 16) * 128 + ks * 32 + a_ko));
            uint32_t b[4][4];
#pragma unroll
            for (int jj = 0; jj < 4; jj++)
                LDSM_X4(b[jj], sB + swz((b_row + jj * 16) * 128 + ks * 32 + b_ko));
#pragma unroll
            for (int mt = 0; mt < 4; mt++)
#pragma unroll
                for (int nt = 0; nt < 8; nt++)
                    MMA16816F(acc[mt][nt], a[mt], b[nt >> 1][(nt & 1) * 2], b[nt >> 1][(nt & 1) * 2 + 1]);
        }
    };

    load_stage(0, 0);
    asm volatile("cp.async.commit_group;" ::: "memory");
    load_stage(1, 1);
    asm volatile("cp.async.commit_group;" ::: "memory");

    for (int kt = 0; kt < KT; kt++) {
        asm volatile("cp.async.wait_group 1;" ::: "memory");
        __syncthreads();
        if (kt + 2 < KT) load_stage((kt + 2) % MSTAGES, kt + 2);
        asm volatile("cp.async.commit_group;" ::: "memory");
        compute(kt % MSTAGES);
    }

    // epilogue: out[row, h] += 0.5 * sum over 8 consecutive cols of acc^2
#pragma unroll
    for (int mt = 0; mt < 4; mt++) {
        const int row  = cm + wm + mt * 16 + (lane >> 2);
        const int row2 = row + 8;
#pragma unroll
        for (int nt = 0; nt < 8; nt++) {
            float s0 = acc[mt][nt][0] * acc[mt][nt][0] + acc[mt][nt][1] * acc[mt][nt][1];
            float s1 = acc[mt][nt][2] * acc[mt][nt][2] + acc[mt][nt][3] * acc[mt][nt][3];
            s0 += __shfl_xor_sync(0xffffffffu, s0, 1);
            s0 += __shfl_xor_sync(0xffffffffu, s0, 2);
            s1 += __shfl_xor_sync(0xffffffffu, s1, 1);
            s1 += __shfl_xor_sync(0xffffffffu, s1, 2);
            if ((lane & 3) == 0) {
                const int h = (cn + wn) / 8 + nt;
                out[(size_t)row  * DH + h] += 0.5f * s0;
                out[(size_t)row2 * DH + h] += 0.5f * s1;
            }
        }
    }
}

// ------------------------------- aux GEMM (proven) --------------------------

__global__ void __launch_bounds__(128, 2)
fm_aux(const __half* __restrict__ gA, const __half* __restrict__ gB,
       float* __restrict__ out, const float* __restrict__ bias)
{
    extern __shared__ __align__(128) char smem[];
    const uint32_t sb = (uint32_t)__cvta_generic_to_shared(smem);
    const int tid = threadIdx.x, lane = tid & 31, wid = tid >> 5;
    const int cm = blockIdx.y * 128, cn = blockIdx.x * 128;
    const int wm = (wid & 1) * 64, wn = (wid >> 1) * 64;
    constexpr int Kld = 1024, KT = 16;

    const int lrow = tid >> 3;
    const int lchunk = tid & 7;
    const __half* gArow = gA + (size_t)(cm + lrow) * Kld + lchunk * 8;
    const __half* gBrow = gB + (size_t)(cn + lrow) * Kld + lchunk * 8;

    const int a_row = wm + (lane & 15);
    const int a_ko  = ((lane >> 4) & 1) * 16;
    const int b_mi  = lane >> 3;
    const int b_row = wn + ((b_mi >> 1) & 1) * 8 + (lane & 7);
    const int b_ko  = (b_mi & 1) * 16;

    float acc[4][8][4];
#pragma unroll
    for (int i = 0; i < 4; i++)
#pragma unroll
        for (int j = 0; j < 8; j++)
#pragma unroll
            for (int q = 0; q < 4; q++) acc[i][j][q] = 0.f;

    auto load_stage = [&](int s, int kt) {
        const uint32_t sa = sb + s * TILEB;
        const uint32_t sB = sb + 3 * TILEB + s * TILEB;
        const int koff = kt * 64;
#pragma unroll
        for (int i = 0; i < 8; i++) {
            uint32_t off = swz((lrow + i * 16) * 128 + lchunk * 16);
            const void* ga = gArow + (size_t)(i * 16) * Kld + koff;
            asm volatile("cp.async.cg.shared.global [%0], [%1], 16;" :: "r"(sa + off), "l"(ga));
            const void* gb = gBrow + (size_t)(i * 16) * Kld + koff;
            asm volatile("cp.async.cg.shared.global [%0], [%1], 16;" :: "r"(sB + off), "l"(gb));
        }
    };

    auto compute = [&](int s) {
        const uint32_t sa = sb + s * TILEB;
        const uint32_t sB = sb + 3 * TILEB + s * TILEB;
#pragma unroll
        for (int ks = 0; ks < 4; ks++) {
            uint32_t a[4][4];
#pragma unroll
            for (int mt = 0; mt < 4; mt++)
                LDSM_X4(a[mt], sa + swz((a_row + mt * 16) * 128 + ks * 32 + a_ko));
            uint32_t b[4][4];
#pragma unroll
            for (int jj = 0; jj < 4; jj++)
                LDSM_X4(b[jj], sB + swz((b_row + jj * 16) * 128 + ks * 32 + b_ko));
#pragma unroll
            for (int mt = 0; mt < 4; mt++)
#pragma unroll
                for (int nt = 0; nt < 8; nt++)
                    MMA16816F(acc[mt][nt], a[mt], b[nt >> 1][(nt & 1) * 2], b[nt >> 1][(nt & 1) * 2 + 1]);
        }
    };

    load_stage(0, 0);
    asm volatile("cp.async.commit_group;" ::: "memory");
    load_stage(1, 1);
    asm volatile("cp.async.commit_group;" ::: "memory");

    for (int kt = 0; kt < KT; kt++) {
        asm volatile("cp.async.wait_group 1;" ::: "memory");
        __syncthreads();
        if (kt + 2 < KT) load_stage((kt + 2) % 3, kt + 2);
        asm volatile("cp.async.commit_group;" ::: "memory");
        compute(kt % 3);
    }

#pragma unroll
    for (int mt = 0; mt < 4; mt++) {
        const int row  = cm + wm + mt * 16 + (lane >> 2);
        const int row2 = row + 8;
#pragma unroll
        for (int nt = 0; nt < 8; nt++) {
            const int col = cn + wn + nt * 8 + (lane & 3) * 2;
            float2 bb = *(const float2*)(bias + col);
            float2 v0 = { acc[mt][nt][0] + bb.x, acc[mt][nt][1] + bb.y };
            float2 v1 = { acc[mt][nt][2] + bb.x, acc[mt][nt][3] + bb.y };
            *(float2*)(out + (size_t)row  * DH + col) = v0;
            *(float2*)(out + (size_t)row2 * DH + col) = v1;
        }
    }
}

// --------------------------------- host side --------------------------------

extern "C" void kernel_launch(void* const* d_in, const int* in_sizes, int n_in,
                              void* d_out, int out_size) {
    const float* x    = (const float*)d_in[0];
    const float* beta = (const float*)d_in[1];
    const float* W    = (const float*)d_in[2];
    const float* bias = (const float*)d_in[3];
    float* out = (float*)d_out;
    (void)in_sizes; (void)n_in; (void)out_size;

    void *pBh, *pAa, *pBa;
    cudaGetSymbolAddress(&pBh, g_Bh);
    cudaGetSymbolAddress(&pAa, g_Aa);
    cudaGetSymbolAddress(&pBa, g_Ba);

    cudaFuncSetAttribute((const void*)fm_main,
                         cudaFuncAttributeMaxDynamicSharedMemorySize, SMEM_GEMM);
    cudaFuncSetAttribute((const void*)fm_aux,
                         cudaFuncAttributeMaxDynamicSharedMemorySize, SMEM_GEMM);

    prep_A <<<(DB * DN) / 256, 256>>>(x);
    prep_Bh<<<(RM * DN) / (256 * 4), 256>>>(beta);
    prep_Ba<<<(DH * DN) / 256, 256>>>(beta, W);

    // aux first: writes every out element (= linear + bias - 0.5*ssq)
    fm_aux<<<dim3(DH / 128, DB / 128), 128, SMEM_GEMM>>>(
        (const __half*)pAa, (const __half*)pBa, out, bias);
    // main: read-modify-write adds 0.5 * sum_l s^2
    fm_main<<<dim3(RM / 128, DB / 128), 128, SMEM_GEMM>>>(
        (const __half*)pAa, (const __half*)pBh, out);
}

// round 13
// speedup vs baseline: 1.0696x; 1.0696x over previous
#include <cuda_runtime.h>
#include <cuda_fp16.h>
#include <cstdint>

// ---------------------------------------------------------------------------
// FactorizedLayer on GB300 (sm_103a) — R13: persistent main GEMM
// out[b,h] = 0.5*sum_l[(x.beta_hl)^2 - (x^2.beta_hl^2)] + x.W_h + b_h
// main: S ~= Xh @ Bh^T (single fp16 product, rel_err ~3e-4). R11 tile shape
//       (CTA 128x64, 4 warps of 64x32) but 296 persistent CTAs grid-striding
//       4096 tiles; cp.async pipeline runs continuously across tile
//       boundaries, amortizing prologue/epilogue 4096 -> 296.
// aux (fp16 K=1024, f32 acc): out = [Xh|X^2].[W|-0.5G]^T + bias  (proven)
// ---------------------------------------------------------------------------

#define DB 4096
#define DN 512
#define DH 1024
#define DL 8
#define RM (DH*DL)

__device__ __align__(16) __half g_Xh[(size_t)DB * 512];    // x hi digit
__device__ __align__(16) __half g_Bh[(size_t)RM * 512];    // beta hi digit
__device__ __align__(16) __half g_Aa[(size_t)DB * 1024];   // [Xh512|X2 512]
__device__ __align__(16) __half g_Ba[(size_t)DH * 1024];   // [Wh512|G512]

// ------------------------------- prep kernels ------------------------------

__global__ void prep_A(const float* __restrict__ x) {
    int i = blockIdx.x * 256 + threadIdx.x;          // over 4096*512
    int m = i >> 9, n = i & 511;
    float v = x[i];
    __half h = __float2half(v);
    g_Xh[(size_t)m * 512 + n] = h;
    size_t ba = (size_t)m * 1024;
    g_Aa[ba + n] = h;
    g_Aa[ba + 512 + n] = __float2half(v * v);
}

__global__ void prep_Bh(const float* __restrict__ beta) {
    int i = blockIdx.x * 256 + threadIdx.x;          // over 8192*512
    g_Bh[i] = __float2half(beta[i]);
}

__global__ void prep_Ba(const float* __restrict__ beta, const float* __restrict__ W) {
    int i = blockIdx.x * 256 + threadIdx.x;          // over 1024*512
    int hh = i >> 9, n = i & 511;
    float w = W[i];
    const float* bp = beta + (size_t)hh * (DL * DN) + n;
    float g = 0.f;
#pragma unroll
    for (int l = 0; l < DL; l++) { float t = bp[l * DN]; g += t * t; }
    g *= -0.5f;
    size_t b = (size_t)hh * 1024;
    g_Ba[b + n] = __float2half(w);
    g_Ba[b + 512 + n] = __float2half(g);
}

// ------------------------------- common -----------------------------------

__device__ __forceinline__ uint32_t swz(uint32_t o) { return o ^ ((o >> 3) & 0x70); }

#define LDSM_X4(r, a)                                                           \
    asm volatile("ldmatrix.sync.aligned.m8n8.x4.shared.b16 {%0,%1,%2,%3}, [%4];"\
        : "=r"((r)[0]), "=r"((r)[1]), "=r"((r)[2]), "=r"((r)[3]) : "r"(a))

#define MMA16816F(c, a, b0, b1)                                                 \
    asm volatile("mma.sync.aligned.m16n8k16.row.col.f32.f16.f16.f32 "           \
        "{%0,%1,%2,%3}, {%4,%5,%6,%7}, {%8,%9}, {%0,%1,%2,%3};"                 \
        : "+f"((c)[0]), "+f"((c)[1]), "+f"((c)[2]), "+f"((c)[3])                 \
        : "r"((a)[0]), "r"((a)[1]), "r"((a)[2]), "r"((a)[3]), "r"(b0), "r"(b1))

// ------------------------------- main GEMM (persistent) --------------------
// 4096 tiles: t -> cm = (t>>7)*128, cn = (t&127)*64. CTA handles t = bid+i*296.
// Global stage index g = i*8 + kt; pipeline ring runs across tile boundaries.

constexpr int ATILE = 16384;   // 128 rows x 128B
constexpr int BTILE = 8192;    // 64 rows x 128B
constexpr int MSTAGES = 3;
constexpr int SMEM_MAIN = MSTAGES * (ATILE + BTILE);   // 73728 -> 2 CTA/SM
constexpr int NCTA = 296;                               // 2 x 148 SMs
constexpr int NTILES = (RM / 64) * (DB / 128);          // 4096

__global__ void __launch_bounds__(128, 2)
fm_main(const __half* __restrict__ gA, const __half* __restrict__ gB,
        float* __restrict__ out)
{
    extern __shared__ __align__(128) char smem[];
    const uint32_t sb = (uint32_t)__cvta_generic_to_shared(smem);
    const int tid = threadIdx.x, lane = tid & 31, wid = tid >> 5;
    const int bid = blockIdx.x;
    const int wm = (wid & 1) * 64, wn = (wid >> 1) * 32;

    const int lrow = tid >> 3;          // 0..15
    const int lchunk = tid & 7;

    const int a_row = wm + (lane & 15);
    const int a_ko  = ((lane >> 4) & 1) * 16;
    const int b_mi  = lane >> 3;
    const int b_row = wn + ((b_mi >> 1) & 1) * 8 + (lane & 7);
    const int b_ko  = (b_mi & 1) * 16;

    const int ntile = (NTILES - bid + NCTA - 1) / NCTA;   // 13 or 14
    const int Gtot = ntile * 8;

    float acc[4][4][4];
#pragma unroll
    for (int i = 0; i < 4; i++)
#pragma unroll
        for (int j = 0; j < 4; j++)
#pragma unroll
            for (int q = 0; q < 4; q++) acc[i][j][q] = 0.f;

    auto load_g = [&](int s, int g) {
        const int t  = bid + (g >> 3) * NCTA;
        const int kt = g & 7;
        const int cm = (t >> 7) * 128;
        const int cn = (t & 127) * 64;
        const uint32_t sa = sb + s * ATILE;
        const uint32_t sB = sb + MSTAGES * ATILE + s * BTILE;
        const __half* gArow = gA + (size_t)(cm + lrow) * 512 + lchunk * 8 + kt * 64;
        const __half* gBrow = gB + (size_t)(cn + lrow) * 512 + lchunk * 8 + kt * 64;
#pragma unroll
        for (int i = 0; i < 8; i++) {   // A: 128 rows
            uint32_t off = swz((lrow + i * 16) * 128 + lchunk * 16);
            const void* ga = gArow + (size_t)(i * 16) * 512;
            asm volatile("cp.async.cg.shared.global [%0], [%1], 16;" :: "r"(sa + off), "l"(ga));
        }
#pragma unroll
        for (int i = 0; i < 4; i++) {   // B: 64 rows
            uint32_t off = swz((lrow + i * 16) * 128 + lchunk * 16);
            const void* gb = gBrow + (size_t)(i * 16) * 512;
            asm volatile("cp.async.cg.shared.global [%0], [%1], 16;" :: "r"(sB + off), "l"(gb));
        }
    };

    auto compute = [&](int s) {
        const uint32_t sa = sb + s * ATILE;
        const uint32_t sB = sb + MSTAGES * ATILE + s * BTILE;
#pragma unroll
        for (int ks = 0; ks < 4; ks++) {
            uint32_t a[4][4];
#pragma unroll
            for (int mt = 0; mt < 4; mt++)
                LDSM_X4(a[mt], sa + swz((a_row + mt * 16) * 128 + ks * 32 + a_ko));
            uint32_t b[2][4];
#pragma unroll
            for (int jj = 0; jj < 2; jj++)
                LDSM_X4(b[jj], sB + swz((b_row + jj * 16) * 128 + ks * 32 + b_ko));
#pragma unroll
            for (int mt = 0; mt < 4; mt++)
#pragma unroll
                for (int nt = 0; nt < 4; nt++)
                    MMA16816F(acc[mt][nt], a[mt], b[nt >> 1][(nt & 1) * 2], b[nt >> 1][(nt & 1) * 2 + 1]);
        }
    };

    load_g(0, 0);
    asm volatile("cp.async.commit_group;" ::: "memory");
    load_g(1, 1);
    asm volatile("cp.async.commit_group;" ::: "memory");

    int sring = 0;
    for (int g = 0; g < Gtot; g++) {
        asm volatile("cp.async.wait_group 1;" ::: "memory");
        __syncthreads();
        if (g + 2 < Gtot) load_g((g + 2) % MSTAGES, g + 2);
        asm volatile("cp.async.commit_group;" ::: "memory");
        compute(sring);
        if (++sring == MSTAGES) sring = 0;

        if ((g & 7) == 7) {
            // epilogue for tile just finished (loads for next tile in flight)
            const int t  = bid + (g >> 3) * NCTA;
            const int cm = (t >> 7) * 128;
            const int cn = (t & 127) * 64;
#pragma unroll
            for (int mt = 0; mt < 4; mt++) {
                const int row  = cm + wm + mt * 16 + (lane >> 2);
                const int row2 = row + 8;
#pragma unroll
                for (int nt = 0; nt < 4; nt++) {
                    float s0 = acc[mt][nt][0] * acc[mt][nt][0] + acc[mt][nt][1] * acc[mt][nt][1];
                    float s1 = acc[mt][nt][2] * acc[mt][nt][2] + acc[mt][nt][3] * acc[mt][nt][3];
                    s0 += __shfl_xor_sync(0xffffffffu, s0, 1);
                    s0 += __shfl_xor_sync(0xffffffffu, s0, 2);
                    s1 += __shfl_xor_sync(0xffffffffu, s1, 1);
                    s1 += __shfl_xor_sync(0xffffffffu, s1, 2);
                    if ((lane & 3) == 0) {
                        const int h = (cn + wn) / 8 + nt;
                        out[(size_t)row  * DH + h] += 0.5f * s0;
                        out[(size_t)row2 * DH + h] += 0.5f * s1;
                    }
#pragma unroll
                    for (int q = 0; q < 4; q++) acc[mt][nt][q] = 0.f;
                }
            }
        }
    }
}

// ------------------------------- aux GEMM (proven, unchanged) ---------------

constexpr int TILEB = 16384;
constexpr int SMEM_AUX = 3 * TILEB * 2;      // 98304

__global__ void __launch_bounds__(128, 2)
fm_aux(const __half* __restrict__ gA, const __half* __restrict__ gB,
       float* __restrict__ out, const float* __restrict__ bias)
{
    extern __shared__ __align__(128) char smem[];
    const uint32_t sb = (uint32_t)__cvta_generic_to_shared(smem);
    const int tid = threadIdx.x, lane = tid & 31, wid = tid >> 5;
    const int cm = blockIdx.y * 128, cn = blockIdx.x * 128;
    const int wm = (wid & 1) * 64, wn = (wid >> 1) * 64;
    constexpr int Kld = 1024, KT = 16;

    const int lrow = tid >> 3;
    const int lchunk = tid & 7;
    const __half* gArow = gA + (size_t)(cm + lrow) * Kld + lchunk * 8;
    const __half* gBrow = gB + (size_t)(cn + lrow) * Kld + lchunk * 8;

    const int a_row = wm + (lane & 15);
    const int a_ko  = ((lane >> 4) & 1) * 16;
    const int b_mi  = lane >> 3;
    const int b_row = wn + ((b_mi >> 1) & 1) * 8 + (lane & 7);
    const int b_ko  = (b_mi & 1) * 16;

    float acc[4][8][4];
#pragma unroll
    for (int i = 0; i < 4; i++)
#pragma unroll
        for (int j = 0; j < 8; j++)
#pragma unroll
            for (int q = 0; q < 4; q++) acc[i][j][q] = 0.f;

    auto load_stage = [&](int s, int kt) {
        const uint32_t sa = sb + s * TILEB;
        const uint32_t sB = sb + 3 * TILEB + s * TILEB;
        const int koff = kt * 64;
#pragma unroll
        for (int i = 0; i < 8; i++) {
            uint32_t off = swz((lrow + i * 16) * 128 + lchunk * 16);
            const void* ga = gArow + (size_t)(i * 16) * Kld + koff;
            asm volatile("cp.async.cg.shared.global [%0], [%1], 16;" :: "r"(sa + off), "l"(ga));
            const void* gb = gBrow + (size_t)(i * 16) * Kld + koff;
            asm volatile("cp.async.cg.shared.global [%0], [%1], 16;" :: "r"(sB + off), "l"(gb));
        }
    };

    auto compute = [&](int s) {
        const uint32_t sa = sb + s * TILEB;
        const uint32_t sB = sb + 3 * TILEB + s * TILEB;
#pragma unroll
        for (int ks = 0; ks < 4; ks++) {
            uint32_t a[4][4];
#pragma unroll
            for (int mt = 0; mt < 4; mt++)
                LDSM_X4(a[mt], sa + swz((a_row + mt * 16) * 128 + ks * 32 + a_ko));
            uint32_t b[4][4];
#pragma unroll
            for (int jj = 0; jj < 4; jj++)
                LDSM_X4(b[jj], sB + swz((b_row + jj * 16) * 128 + ks * 32 + b_ko));
#pragma unroll
            for (int mt = 0; mt < 4; mt++)
#pragma unroll
                for (int nt = 0; nt < 8; nt++)
                    MMA16816F(acc[mt][nt], a[mt], b[nt >> 1][(nt & 1) * 2], b[nt >> 1][(nt & 1) * 2 + 1]);
        }
    };

    load_stage(0, 0);
    asm volatile("cp.async.commit_group;" ::: "memory");
    load_stage(1, 1);
    asm volatile("cp.async.commit_group;" ::: "memory");

    for (int kt = 0; kt < KT; kt++) {
        asm volatile("cp.async.wait_group 1;" ::: "memory");
        __syncthreads();
        if (kt + 2 < KT) load_stage((kt + 2) % 3, kt + 2);
        asm volatile("cp.async.commit_group;" ::: "memory");
        compute(kt % 3);
    }

#pragma unroll
    for (int mt = 0; mt < 4; mt++) {
        const int row  = cm + wm + mt * 16 + (lane >> 2);
        const int row2 = row + 8;
#pragma unroll
        for (int nt = 0; nt < 8; nt++) {
            const int col = cn + wn + nt * 8 + (lane & 3) * 2;
            float2 bb = *(const float2*)(bias + col);
            float2 v0 = { acc[mt][nt][0] + bb.x, acc[mt][nt][1] + bb.y };
            float2 v1 = { acc[mt][nt][2] + bb.x, acc[mt][nt][3] + bb.y };
            *(float2*)(out + (size_t)row  * DH + col) = v0;
            *(float2*)(out + (size_t)row2 * DH + col) = v1;
        }
    }
}

// --------------------------------- host side --------------------------------

extern "C" void kernel_launch(void* const* d_in, const int* in_sizes, int n_in,
                              void* d_out, int out_size) {
    const float* x    = (const float*)d_in[0];
    const float* beta = (const float*)d_in[1];
    const float* W    = (const float*)d_in[2];
    const float* bias = (const float*)d_in[3];
    float* out = (float*)d_out;
    (void)in_sizes; (void)n_in; (void)out_size;

    void *pXh, *pBh, *pAa, *pBa;
    cudaGetSymbolAddress(&pXh, g_Xh);
    cudaGetSymbolAddress(&pBh, g_Bh);
    cudaGetSymbolAddress(&pAa, g_Aa);
    cudaGetSymbolAddress(&pBa, g_Ba);

    cudaFuncSetAttribute((const void*)fm_main,
                         cudaFuncAttributeMaxDynamicSharedMemorySize, SMEM_MAIN);
    cudaFuncSetAttribute((const void*)fm_aux,
                         cudaFuncAttributeMaxDynamicSharedMemorySize, SMEM_AUX);

    prep_A <<<(DB * DN) / 256, 256>>>(x);
    prep_Bh<<<(RM * DN) / 256, 256>>>(beta);
    prep_Ba<<<(DH * DN) / 256, 256>>>(beta, W);

    // aux first: writes every out element (= linear + bias - 0.5*ssq)
    fm_aux<<<dim3(DH / 128, DB / 128), 128, SMEM_AUX>>>(
        (const __half*)pAa, (const __half*)pBa, out, bias);
    // main: persistent CTAs add 0.5 * sum_l s^2 (RMW)
    fm_main<<<NCTA, 128, SMEM_MAIN>>>(
        (const __half*)pXh, (const __half*)pBh, out);
}

// round 14
// speedup vs baseline: 1.2214x; 1.1420x over previous
#include <cuda_runtime.h>
#include <cuda_fp16.h>
#include <cstdint>

// ---------------------------------------------------------------------------
// FactorizedLayer on GB300 (sm_103a) — R14: R4 geometry + R11 precision
// out[b,h] = 0.5*sum_l[(x.beta_hl)^2 - (x^2.beta_hl^2)] + x.W_h + b_h
// Best-measured GEMM shape (R4): CTA 128x128, 256 thr, 8 warps of 64x32,
// 3-stage cp.async, 2 CTA/SM (11.8 ns/M-MMA). Single fp16 product main
// (rel_err ~3e-4, calibrated). aux: K=1024 [Xh|X^2].[W|-0.5G]^T + bias.
// ---------------------------------------------------------------------------

#define DB 4096
#define DN 512
#define DH 1024
#define DL 8
#define RM (DH*DL)

__device__ __align__(16) __half g_Xh[(size_t)DB * 512];    // x hi digit
__device__ __align__(16) __half g_Bh[(size_t)RM * 512];    // beta hi digit
__device__ __align__(16) __half g_Aa[(size_t)DB * 1024];   // [Xh512|X2 512]
__device__ __align__(16) __half g_Ba[(size_t)DH * 1024];   // [Wh512|G512]

// ------------------------------- prep kernels ------------------------------

__global__ void prep_A(const float* __restrict__ x) {
    int i = blockIdx.x * 256 + threadIdx.x;          // over 4096*512
    int m = i >> 9, n = i & 511;
    float v = x[i];
    __half h = __float2half(v);
    g_Xh[(size_t)m * 512 + n] = h;
    size_t ba = (size_t)m * 1024;
    g_Aa[ba + n] = h;
    g_Aa[ba + 512 + n] = __float2half(v * v);
}

__global__ void prep_Bh(const float* __restrict__ beta) {
    int i = blockIdx.x * 256 + threadIdx.x;          // over (8192*512)/4 float4s
    float4 v = ((const float4*)beta)[i];
    __half2* dst = (__half2*)g_Bh;
    dst[i * 2 + 0] = __floats2half2_rn(v.x, v.y);
    dst[i * 2 + 1] = __floats2half2_rn(v.z, v.w);
}

__global__ void prep_Ba(const float* __restrict__ beta, const float* __restrict__ W) {
    int i = blockIdx.x * 256 + threadIdx.x;          // over 1024*512
    int hh = i >> 9, n = i & 511;
    float w = W[i];
    const float* bp = beta + (size_t)hh * (DL * DN) + n;
    float g = 0.f;
#pragma unroll
    for (int l = 0; l < DL; l++) { float t = bp[l * DN]; g += t * t; }
    g *= -0.5f;
    size_t b = (size_t)hh * 1024;
    g_Ba[b + n] = __float2half(w);
    g_Ba[b + 512 + n] = __float2half(g);
}

// ------------------------------- common -----------------------------------

__device__ __forceinline__ uint32_t swz(uint32_t o) { return o ^ ((o >> 3) & 0x70); }

constexpr int STAGES = 3;
constexpr int TILEB = 16384;                 // 128 rows x 128B per operand/stage
constexpr int SMEMB = STAGES * TILEB * 2;    // 98304 -> 2 CTAs/SM

#define LDSM_X4(r, a)                                                           \
    asm volatile("ldmatrix.sync.aligned.m8n8.x4.shared.b16 {%0,%1,%2,%3}, [%4];"\
        : "=r"((r)[0]), "=r"((r)[1]), "=r"((r)[2]), "=r"((r)[3]) : "r"(a))

#define MMA16816F(c, a, b0, b1)                                                 \
    asm volatile("mma.sync.aligned.m16n8k16.row.col.f32.f16.f16.f32 "           \
        "{%0,%1,%2,%3}, {%4,%5,%6,%7}, {%8,%9}, {%0,%1,%2,%3};"                 \
        : "+f"((c)[0]), "+f"((c)[1]), "+f"((c)[2]), "+f"((c)[3])                 \
        : "r"((a)[0]), "r"((a)[1]), "r"((a)[2]), "r"((a)[3]), "r"(b0), "r"(b1))

// MODE 0: aux (out = acc + bias[col]); MODE 1: main (out += 0.5*sum8(acc^2))
// CTA 128x128, 8 warps (2 x 4) of 64x32 tiles, 256 threads.
template <int MODE>
__global__ void __launch_bounds__(256, 2)
fm_gemm(const __half* __restrict__ gA, const __half* __restrict__ gB,
        float* __restrict__ out, const float* __restrict__ bias, int Kld, int KT)
{
    extern __shared__ __align__(128) char smem[];
    const uint32_t sb = (uint32_t)__cvta_generic_to_shared(smem);
    const int tid = threadIdx.x, lane = tid & 31, wid = tid >> 5;
    const int cm = blockIdx.y * 128, cn = blockIdx.x * 128;
    const int wm = (wid & 1) * 64, wn = (wid >> 1) * 32;

    // cp.async lane mapping: 32 rows x 8 chunks of 16B per pass, 4 passes
    const int lrow = tid >> 3;
    const int lchunk = tid & 7;
    const __half* gArow = gA + (size_t)(cm + lrow) * Kld + lchunk * 8;
    const __half* gBrow = gB + (size_t)(cn + lrow) * Kld + lchunk * 8;

    const int a_row = wm + (lane & 15);
    const int a_ko  = ((lane >> 4) & 1) * 16;
    const int b_mi  = lane >> 3;
    const int b_row = wn + ((b_mi >> 1) & 1) * 8 + (lane & 7);
    const int b_ko  = (b_mi & 1) * 16;

    float acc[4][4][4];
#pragma unroll
    for (int i = 0; i < 4; i++)
#pragma unroll
        for (int j = 0; j < 4; j++)
#pragma unroll
            for (int q = 0; q < 4; q++) acc[i][j][q] = 0.f;

    auto load_stage = [&](int s, int kt) {
        const uint32_t sa = sb + s * TILEB;
        const uint32_t sB = sb + STAGES * TILEB + s * TILEB;
        const int koff = kt * 64;
#pragma unroll
        for (int i = 0; i < 4; i++) {
            uint32_t off = swz((lrow + i * 32) * 128 + lchunk * 16);
            const void* ga = gArow + (size_t)(i * 32) * Kld + koff;
            asm volatile("cp.async.cg.shared.global [%0], [%1], 16;" :: "r"(sa + off), "l"(ga));
            const void* gb = gBrow + (size_t)(i * 32) * Kld + koff;
            asm volatile("cp.async.cg.shared.global [%0], [%1], 16;" :: "r"(sB + off), "l"(gb));
        }
    };

    auto compute = [&](int s) {
        const uint32_t sa = sb + s * TILEB;
        const uint32_t sB = sb + STAGES * TILEB + s * TILEB;
#pragma unroll
        for (int ks = 0; ks < 4; ks++) {
            uint32_t a[4][4];
#pragma unroll
            for (int mt = 0; mt < 4; mt++)
                LDSM_X4(a[mt], sa + swz((a_row + mt * 16) * 128 + ks * 32 + a_ko));
            uint32_t b[2][4];
#pragma unroll
            for (int jj = 0; jj < 2; jj++)
                LDSM_X4(b[jj], sB + swz((b_row + jj * 16) * 128 + ks * 32 + b_ko));
#pragma unroll
            for (int mt = 0; mt < 4; mt++)
#pragma unroll
                for (int nt = 0; nt < 4; nt++)
                    MMA16816F(acc[mt][nt], a[mt], b[nt >> 1][(nt & 1) * 2], b[nt >> 1][(nt & 1) * 2 + 1]);
        }
    };

    load_stage(0, 0);
    asm volatile("cp.async.commit_group;" ::: "memory");
    load_stage(1, 1);
    asm volatile("cp.async.commit_group;" ::: "memory");

    for (int kt = 0; kt < KT; kt++) {
        asm volatile("cp.async.wait_group 1;" ::: "memory");
        __syncthreads();
        if (kt + 2 < KT) load_stage((kt + 2) % STAGES, kt + 2);
        asm volatile("cp.async.commit_group;" ::: "memory");
        compute(kt % STAGES);
    }

    // ------------------------------ epilogue ------------------------------
#pragma unroll
    for (int mt = 0; mt < 4; mt++) {
        const int row  = cm + wm + mt * 16 + (lane >> 2);
        const int row2 = row + 8;
#pragma unroll
        for (int nt = 0; nt < 4; nt++) {
            if (MODE == 0) {
                const int col = cn + wn + nt * 8 + (lane & 3) * 2;
                float2 bb = *(const float2*)(bias + col);
                float2 v0 = { acc[mt][nt][0] + bb.x, acc[mt][nt][1] + bb.y };
                float2 v1 = { acc[mt][nt][2] + bb.x, acc[mt][nt][3] + bb.y };
                *(float2*)(out + (size_t)row  * DH + col) = v0;
                *(float2*)(out + (size_t)row2 * DH + col) = v1;
            } else {
                float s0 = acc[mt][nt][0] * acc[mt][nt][0] + acc[mt][nt][1] * acc[mt][nt][1];
                float s1 = acc[mt][nt][2] * acc[mt][nt][2] + acc[mt][nt][3] * acc[mt][nt][3];
                s0 += __shfl_xor_sync(0xffffffffu, s0, 1);
                s0 += __shfl_xor_sync(0xffffffffu, s0, 2);
                s1 += __shfl_xor_sync(0xffffffffu, s1, 1);
                s1 += __shfl_xor_sync(0xffffffffu, s1, 2);
                if ((lane & 3) == 0) {
                    const int h = (cn + wn) / 8 + nt;
                    out[(size_t)row  * DH + h] += 0.5f * s0;
                    out[(size_t)row2 * DH + h] += 0.5f * s1;
                }
            }
        }
    }
}

// --------------------------------- host side --------------------------------

extern "C" void kernel_launch(void* const* d_in, const int* in_sizes, int n_in,
                              void* d_out, int out_size) {
    const float* x    = (const float*)d_in[0];
    const float* beta = (const float*)d_in[1];
    const float* W    = (const float*)d_in[2];
    const float* bias = (const float*)d_in[3];
    float* out = (float*)d_out;
    (void)in_sizes; (void)n_in; (void)out_size;

    void *pXh, *pBh, *pAa, *pBa;
    cudaGetSymbolAddress(&pXh, g_Xh);
    cudaGetSymbolAddress(&pBh, g_Bh);
    cudaGetSymbolAddress(&pAa, g_Aa);
    cudaGetSymbolAddress(&pBa, g_Ba);

    cudaFuncSetAttribute((const void*)fm_gemm<0>,
                         cudaFuncAttributeMaxDynamicSharedMemorySize, SMEMB);
    cudaFuncSetAttribute((const void*)fm_gemm<1>,
                         cudaFuncAttributeMaxDynamicSharedMemorySize, SMEMB);

    prep_A <<<(DB * DN) / 256, 256>>>(x);
    prep_Bh<<<(RM * DN) / (256 * 4), 256>>>(beta);
    prep_Ba<<<(DH * DN) / 256, 256>>>(beta, W);

    // aux first: writes every out element (= linear + bias - 0.5*ssq)
    fm_gemm<0><<<dim3(DH / 128, DB / 128), 256, SMEMB>>>(
        (const __half*)pAa, (const __half*)pBa, out, bias, 1024, 16);
    // main: read-modify-write adds 0.5 * sum_l s^2
    fm_gemm<1><<<dim3(RM / 128, DB / 128), 256, SMEMB>>>(
        (const __half*)pXh, (const __half*)pBh, out, bias, 512, 8);
}

// round 16
// speedup vs baseline: 1.7677x; 1.4473x over previous
#include <cuda_runtime.h>
#include <cuda_fp16.h>
#include <cstdint>

// ---------------------------------------------------------------------------
// FactorizedLayer on GB300 (sm_103a) — R16: R15 epilogue restructure, B-stride
// bug fixed (aux B stride is 1024; now passed as KldB parameter).
// out[b,h] = 0.5*sum_l[(x.beta_hl)^2 - (x^2.beta_hl^2)] + x.W_h + b_h
// main FIRST (single fp16 product S~=Xh@Bh^T): pure-store float4 epilogue.
// aux second: coalesced float2 RMW adds linear + bias - 0.5*ssq.
// GEMM geometry: CTA 128x128, 256 thr, 8 warps 64x32, 3-stage, 2 CTA/SM.
// ---------------------------------------------------------------------------

#define DB 4096
#define DN 512
#define DH 1024
#define DL 8
#define RM (DH*DL)

__device__ __align__(16) __half g_Bh[(size_t)RM * 512];    // beta hi digit
__device__ __align__(16) __half g_Aa[(size_t)DB * 1024];   // [Xh512|X2 512]
__device__ __align__(16) __half g_Ba[(size_t)DH * 1024];   // [Wh512|G512]

// ------------------------------- prep kernels ------------------------------

__global__ void prep_A(const float* __restrict__ x) {
    int i = blockIdx.x * 256 + threadIdx.x;          // over 4096*512
    int m = i >> 9, n = i & 511;
    float v = x[i];
    size_t ba = (size_t)m * 1024;
    g_Aa[ba + n] = __float2half(v);
    g_Aa[ba + 512 + n] = __float2half(v * v);
}

__global__ void prep_Bh(const float* __restrict__ beta) {
    int i = blockIdx.x * 256 + threadIdx.x;          // over (8192*512)/4 float4s
    float4 v = ((const float4*)beta)[i];
    __half2* dst = (__half2*)g_Bh;
    dst[i * 2 + 0] = __floats2half2_rn(v.x, v.y);
    dst[i * 2 + 1] = __floats2half2_rn(v.z, v.w);
}

__global__ void prep_Ba(const float* __restrict__ beta, const float* __restrict__ W) {
    int i = blockIdx.x * 256 + threadIdx.x;          // over 1024*512
    int hh = i >> 9, n = i & 511;
    float w = W[i];
    const float* bp = beta + (size_t)hh * (DL * DN) + n;
    float g = 0.f;
#pragma unroll
    for (int l = 0; l < DL; l++) { float t = bp[l * DN]; g += t * t; }
    g *= -0.5f;
    size_t b = (size_t)hh * 1024;
    g_Ba[b + n] = __float2half(w);
    g_Ba[b + 512 + n] = __float2half(g);
}

// ------------------------------- common -----------------------------------

__device__ __forceinline__ uint32_t swz(uint32_t o) { return o ^ ((o >> 3) & 0x70); }

constexpr int STAGES = 3;
constexpr int TILEB = 16384;                 // 128 rows x 128B per operand/stage
constexpr int SMEMB = STAGES * TILEB * 2;    // 98304 -> 2 CTAs/SM

#define LDSM_X4(r, a)                                                           \
    asm volatile("ldmatrix.sync.aligned.m8n8.x4.shared.b16 {%0,%1,%2,%3}, [%4];"\
        : "=r"((r)[0]), "=r"((r)[1]), "=r"((r)[2]), "=r"((r)[3]) : "r"(a))

#define MMA16816F(c, a, b0, b1)                                                 \
    asm volatile("mma.sync.aligned.m16n8k16.row.col.f32.f16.f16.f32 "           \
        "{%0,%1,%2,%3}, {%4,%5,%6,%7}, {%8,%9}, {%0,%1,%2,%3};"                 \
        : "+f"((c)[0]), "+f"((c)[1]), "+f"((c)[2]), "+f"((c)[3])                 \
        : "r"((a)[0]), "r"((a)[1]), "r"((a)[2]), "r"((a)[3]), "r"(b0), "r"(b1))

// MODE 1: main (runs first; out = 0.5*sum8(acc^2), pure float4 stores)
// MODE 0: aux  (runs second; out += acc + bias[col], coalesced float2 RMW)
// CTA 128x128, 8 warps (2 x 4) of 64x32 tiles, 256 threads.
template <int MODE>
__global__ void __launch_bounds__(256, 2)
fm_gemm(const __half* __restrict__ gA, const __half* __restrict__ gB,
        float* __restrict__ out, const float* __restrict__ bias,
        int KldA, int KldB, int KT)
{
    extern __shared__ __align__(128) char smem[];
    const uint32_t sb = (uint32_t)__cvta_generic_to_shared(smem);
    const int tid = threadIdx.x, lane = tid & 31, wid = tid >> 5;
    const int cm = blockIdx.y * 128, cn = blockIdx.x * 128;
    const int wm = (wid & 1) * 64, wn = (wid >> 1) * 32;

    // cp.async lane mapping: 32 rows x 8 chunks of 16B per pass, 4 passes
    const int lrow = tid >> 3;
    const int lchunk = tid & 7;
    const __half* gArow = gA + (size_t)(cm + lrow) * KldA + lchunk * 8;
    const __half* gBrow = gB + (size_t)(cn + lrow) * KldB + lchunk * 8;

    const int a_row = wm + (lane & 15);
    const int a_ko  = ((lane >> 4) & 1) * 16;
    const int b_mi  = lane >> 3;
    const int b_row = wn + ((b_mi >> 1) & 1) * 8 + (lane & 7);
    const int b_ko  = (b_mi & 1) * 16;

    float acc[4][4][4];
#pragma unroll
    for (int i = 0; i < 4; i++)
#pragma unroll
        for (int j = 0; j < 4; j++)
#pragma unroll
            for (int q = 0; q < 4; q++) acc[i][j][q] = 0.f;

    auto load_stage = [&](int s, int kt) {
        const uint32_t sa = sb + s * TILEB;
        const uint32_t sB = sb + STAGES * TILEB + s * TILEB;
        const int koff = kt * 64;
#pragma unroll
        for (int i = 0; i < 4; i++) {
            uint32_t off = swz((lrow + i * 32) * 128 + lchunk * 16);
            const void* ga = gArow + (size_t)(i * 32) * KldA + koff;
            asm volatile("cp.async.cg.shared.global [%0], [%1], 16;" :: "r"(sa + off), "l"(ga));
            const void* gb = gBrow + (size_t)(i * 32) * KldB + koff;
            asm volatile("cp.async.cg.shared.global [%0], [%1], 16;" :: "r"(sB + off), "l"(gb));
        }
    };

    auto compute = [&](int s) {
        const uint32_t sa = sb + s * TILEB;
        const uint32_t sB = sb + STAGES * TILEB + s * TILEB;
#pragma unroll
        for (int ks = 0; ks < 4; ks++) {
            uint32_t a[4][4];
#pragma unroll
            for (int mt = 0; mt < 4; mt++)
                LDSM_X4(a[mt], sa + swz((a_row + mt * 16) * 128 + ks * 32 + a_ko));
            uint32_t b[2][4];
#pragma unroll
            for (int jj = 0; jj < 2; jj++)
                LDSM_X4(b[jj], sB + swz((b_row + jj * 16) * 128 + ks * 32 + b_ko));
#pragma unroll
            for (int mt = 0; mt < 4; mt++)
#pragma unroll
                for (int nt = 0; nt < 4; nt++)
                    MMA16816F(acc[mt][nt], a[mt], b[nt >> 1][(nt & 1) * 2], b[nt >> 1][(nt & 1) * 2 + 1]);
        }
    };

    load_stage(0, 0);
    asm volatile("cp.async.commit_group;" ::: "memory");
    load_stage(1, 1);
    asm volatile("cp.async.commit_group;" ::: "memory");

    for (int kt = 0; kt < KT; kt++) {
        asm volatile("cp.async.wait_group 1;" ::: "memory");
        __syncthreads();
        if (kt + 2 < KT) load_stage((kt + 2) % STAGES, kt + 2);
        asm volatile("cp.async.commit_group;" ::: "memory");
        compute(kt % STAGES);
    }

    // ------------------------------ epilogue ------------------------------
#pragma unroll
    for (int mt = 0; mt < 4; mt++) {
        const int row  = cm + wm + mt * 16 + (lane >> 2);
        const int row2 = row + 8;
        if (MODE == 0) {
#pragma unroll
            for (int nt = 0; nt < 4; nt++) {
                const int col = cn + wn + nt * 8 + (lane & 3) * 2;
                float2 bb = *(const float2*)(bias + col);
                float2* p0 = (float2*)(out + (size_t)row  * DH + col);
                float2* p1 = (float2*)(out + (size_t)row2 * DH + col);
                float2 o0 = *p0, o1 = *p1;
                o0.x += acc[mt][nt][0] + bb.x;  o0.y += acc[mt][nt][1] + bb.y;
                o1.x += acc[mt][nt][2] + bb.x;  o1.y += acc[mt][nt][3] + bb.y;
                *p0 = o0; *p1 = o1;
            }
        } else {
            float4 v0, v1;
#pragma unroll
            for (int nt = 0; nt < 4; nt++) {
                float s0 = acc[mt][nt][0] * acc[mt][nt][0] + acc[mt][nt][1] * acc[mt][nt][1];
                float s1 = acc[mt][nt][2] * acc[mt][nt][2] + acc[mt][nt][3] * acc[mt][nt][3];
                s0 += __shfl_xor_sync(0xffffffffu, s0, 1);
                s0 += __shfl_xor_sync(0xffffffffu, s0, 2);
                s1 += __shfl_xor_sync(0xffffffffu, s1, 1);
                s1 += __shfl_xor_sync(0xffffffffu, s1, 2);
                ((float*)&v0)[nt] = 0.5f * s0;
                ((float*)&v1)[nt] = 0.5f * s1;
            }
            if ((lane & 3) == 0) {
                const int hb = (cn + wn) / 8;       // multiple of 4
                *(float4*)(out + (size_t)row  * DH + hb) = v0;
                *(float4*)(out + (size_t)row2 * DH + hb) = v1;
            }
        }
    }
}

// --------------------------------- host side --------------------------------

extern "C" void kernel_launch(void* const* d_in, const int* in_sizes, int n_in,
                              void* d_out, int out_size) {
    const float* x    = (const float*)d_in[0];
    const float* beta = (const float*)d_in[1];
    const float* W    = (const float*)d_in[2];
    const float* bias = (const float*)d_in[3];
    float* out = (float*)d_out;
    (void)in_sizes; (void)n_in; (void)out_size;

    void *pBh, *pAa, *pBa;
    cudaGetSymbolAddress(&pBh, g_Bh);
    cudaGetSymbolAddress(&pAa, g_Aa);
    cudaGetSymbolAddress(&pBa, g_Ba);

    cudaFuncSetAttribute((const void*)fm_gemm<0>,
                         cudaFuncAttributeMaxDynamicSharedMemorySize, SMEMB);
    cudaFuncSetAttribute((const void*)fm_gemm<1>,
                         cudaFuncAttributeMaxDynamicSharedMemorySize, SMEMB);

    prep_A <<<(DB * DN) / 256, 256>>>(x);
    prep_Bh<<<(RM * DN) / (256 * 4), 256>>>(beta);
    prep_Ba<<<(DH * DN) / 256, 256>>>(beta, W);

    // main FIRST: pure stores out = 0.5 * sum_l s^2
    // A = g_Aa hi panel (KldA=1024), B = g_Bh (KldB=512), KT=8
    fm_gemm<1><<<dim3(RM / 128, DB / 128), 256, SMEMB>>>(
        (const __half*)pAa, (const __half*)pBh, out, bias, 1024, 512, 8);
    // aux second: coalesced RMW adds linear + bias - 0.5*ssq
    // A = g_Aa (KldA=1024), B = g_Ba (KldB=1024), KT=16
    fm_gemm<0><<<dim3(DH / 128, DB / 128), 256, SMEMB>>>(
        (const __half*)pAa, (const __half*)pBa, out, bias, 1024, 1024, 16);
}

// round 17
// speedup vs baseline: 1.8444x; 1.0434x over previous
#include <cuda_runtime.h>
#include <cuda_fp16.h>
#include <cstdint>

// ---------------------------------------------------------------------------
// FactorizedLayer on GB300 (sm_103a) — R17: fused vectorized prep (1 launch)
// out[b,h] = 0.5*sum_l[(x.beta_hl)^2 - (x^2.beta_hl^2)] + x.W_h + b_h
// main FIRST (single fp16 product S~=Xh@Bh^T): pure-store float4 epilogue.
// aux second: coalesced float2 RMW adds linear + bias - 0.5*ssq.
// GEMMs byte-identical to R16 (127.7us). Prep: 3 scalar kernels -> 1 fused
// float4/half2 kernel (region-split grid).
// ---------------------------------------------------------------------------

#define DB 4096
#define DN 512
#define DH 1024
#define DL 8
#define RM (DH*DL)

__device__ __align__(16) __half g_Bh[(size_t)RM * 512];    // beta hi digit
__device__ __align__(16) __half g_Aa[(size_t)DB * 1024];   // [Xh512|X2 512]
__device__ __align__(16) __half g_Ba[(size_t)DH * 1024];   // [Wh512|G512]

// ------------------------------- fused prep ---------------------------------
// blocks [0,2048):      x -> Aa  (512K float4)
// blocks [2048,6144):   beta -> Bh (1M float4)
// blocks [6144,6656):   W,beta -> Ba (128K float4)

constexpr int PREP_BLOCKS = 6656;

__global__ void __launch_bounds__(256)
prep_all(const float* __restrict__ x, const float* __restrict__ beta,
         const float* __restrict__ W) {
    const int b = blockIdx.x, t = threadIdx.x;
    if (b < 2048) {
        int i = b * 256 + t;                       // float4 index over x
        int m = i >> 7, n4 = (i & 127) * 4;
        float4 v = ((const float4*)x)[i];
        __half2* pa = (__half2*)(g_Aa + (size_t)m * 1024 + n4);
        pa[0] = __floats2half2_rn(v.x, v.y);
        pa[1] = __floats2half2_rn(v.z, v.w);
        __half2* ps = (__half2*)(g_Aa + (size_t)m * 1024 + 512 + n4);
        ps[0] = __floats2half2_rn(v.x * v.x, v.y * v.y);
        ps[1] = __floats2half2_rn(v.z * v.z, v.w * v.w);
    } else if (b < 6144) {
        int i = (b - 2048) * 256 + t;              // float4 index over beta
        float4 v = ((const float4*)beta)[i];
        __half2* dst = (__half2*)g_Bh;
        dst[i * 2 + 0] = __floats2half2_rn(v.x, v.y);
        dst[i * 2 + 1] = __floats2half2_rn(v.z, v.w);
    } else {
        int i = (b - 6144) * 256 + t;              // float4 index over W
        int hh = i >> 7, n4 = (i & 127) * 4;
        float4 w = ((const float4*)W)[i];
        const float* bp = beta + (size_t)hh * (DL * DN) + n4;
        float4 g = make_float4(0.f, 0.f, 0.f, 0.f);
#pragma unroll
        for (int l = 0; l < DL; l++) {
            float4 t4 = *(const float4*)(bp + l * DN);
            g.x += t4.x * t4.x; g.y += t4.y * t4.y;
            g.z += t4.z * t4.z; g.w += t4.w * t4.w;
        }
        g.x *= -0.5f; g.y *= -0.5f; g.z *= -0.5f; g.w *= -0.5f;
        __half2* pw = (__half2*)(g_Ba + (size_t)hh * 1024 + n4);
        pw[0] = __floats2half2_rn(w.x, w.y);
        pw[1] = __floats2half2_rn(w.z, w.w);
        __half2* pg = (__half2*)(g_Ba + (size_t)hh * 1024 + 512 + n4);
        pg[0] = __floats2half2_rn(g.x, g.y);
        pg[1] = __floats2half2_rn(g.z, g.w);
    }
}

// ------------------------------- common -----------------------------------

__device__ __forceinline__ uint32_t swz(uint32_t o) { return o ^ ((o >> 3) & 0x70); }

constexpr int STAGES = 3;
constexpr int TILEB = 16384;                 // 128 rows x 128B per operand/stage
constexpr int SMEMB = STAGES * TILEB * 2;    // 98304 -> 2 CTAs/SM

#define LDSM_X4(r, a)                                                           \
    asm volatile("ldmatrix.sync.aligned.m8n8.x4.shared.b16 {%0,%1,%2,%3}, [%4];"\
        : "=r"((r)[0]), "=r"((r)[1]), "=r"((r)[2]), "=r"((r)[3]) : "r"(a))

#define MMA16816F(c, a, b0, b1)                                                 \
    asm volatile("mma.sync.aligned.m16n8k16.row.col.f32.f16.f16.f32 "           \
        "{%0,%1,%2,%3}, {%4,%5,%6,%7}, {%8,%9}, {%0,%1,%2,%3};"                 \
        : "+f"((c)[0]), "+f"((c)[1]), "+f"((c)[2]), "+f"((c)[3])                 \
        : "r"((a)[0]), "r"((a)[1]), "r"((a)[2]), "r"((a)[3]), "r"(b0), "r"(b1))

// MODE 1: main (runs first; out = 0.5*sum8(acc^2), pure float4 stores)
// MODE 0: aux  (runs second; out += acc + bias[col], coalesced float2 RMW)
// CTA 128x128, 8 warps (2 x 4) of 64x32 tiles, 256 threads.
template <int MODE>
__global__ void __launch_bounds__(256, 2)
fm_gemm(const __half* __restrict__ gA, const __half* __restrict__ gB,
        float* __restrict__ out, const float* __restrict__ bias,
        int KldA, int KldB, int KT)
{
    extern __shared__ __align__(128) char smem[];
    const uint32_t sb = (uint32_t)__cvta_generic_to_shared(smem);
    const int tid = threadIdx.x, lane = tid & 31, wid = tid >> 5;
    const int cm = blockIdx.y * 128, cn = blockIdx.x * 128;
    const int wm = (wid & 1) * 64, wn = (wid >> 1) * 32;

    // cp.async lane mapping: 32 rows x 8 chunks of 16B per pass, 4 passes
    const int lrow = tid >> 3;
    const int lchunk = tid & 7;
    const __half* gArow = gA + (size_t)(cm + lrow) * KldA + lchunk * 8;
    const __half* gBrow = gB + (size_t)(cn + lrow) * KldB + lchunk * 8;

    const int a_row = wm + (lane & 15);
    const int a_ko  = ((lane >> 4) & 1) * 16;
    const int b_mi  = lane >> 3;
    const int b_row = wn + ((b_mi >> 1) & 1) * 8 + (lane & 7);
    const int b_ko  = (b_mi & 1) * 16;

    float acc[4][4][4];
#pragma unroll
    for (int i = 0; i < 4; i++)
#pragma unroll
        for (int j = 0; j < 4; j++)
#pragma unroll
            for (int q = 0; q < 4; q++) acc[i][j][q] = 0.f;

    auto load_stage = [&](int s, int kt) {
        const uint32_t sa = sb + s * TILEB;
        const uint32_t sB = sb + STAGES * TILEB + s * TILEB;
        const int koff = kt * 64;
#pragma unroll
        for (int i = 0; i < 4; i++) {
            uint32_t off = swz((lrow + i * 32) * 128 + lchunk * 16);
            const void* ga = gArow + (size_t)(i * 32) * KldA + koff;
            asm volatile("cp.async.cg.shared.global [%0], [%1], 16;" :: "r"(sa + off), "l"(ga));
            const void* gb = gBrow + (size_t)(i * 32) * KldB + koff;
            asm volatile("cp.async.cg.shared.global [%0], [%1], 16;" :: "r"(sB + off), "l"(gb));
        }
    };

    auto compute = [&](int s) {
        const uint32_t sa = sb + s * TILEB;
        const uint32_t sB = sb + STAGES * TILEB + s * TILEB;
#pragma unroll
        for (int ks = 0; ks < 4; ks++) {
            uint32_t a[4][4];
#pragma unroll
            for (int mt = 0; mt < 4; mt++)
                LDSM_X4(a[mt], sa + swz((a_row + mt * 16) * 128 + ks * 32 + a_ko));
            uint32_t b[2][4];
#pragma unroll
            for (int jj = 0; jj < 2; jj++)
                LDSM_X4(b[jj], sB + swz((b_row + jj * 16) * 128 + ks * 32 + b_ko));
#pragma unroll
            for (int mt = 0; mt < 4; mt++)
#pragma unroll
                for (int nt = 0; nt < 4; nt++)
                    MMA16816F(acc[mt][nt], a[mt], b[nt >> 1][(nt & 1) * 2], b[nt >> 1][(nt & 1) * 2 + 1]);
        }
    };

    load_stage(0, 0);
    asm volatile("cp.async.commit_group;" ::: "memory");
    load_stage(1, 1);
    asm volatile("cp.async.commit_group;" ::: "memory");

    for (int kt = 0; kt < KT; kt++) {
        asm volatile("cp.async.wait_group 1;" ::: "memory");
        __syncthreads();
        if (kt + 2 < KT) load_stage((kt + 2) % STAGES, kt + 2);
        asm volatile("cp.async.commit_group;" ::: "memory");
        compute(kt % STAGES);
    }

    // ------------------------------ epilogue ------------------------------
#pragma unroll
    for (int mt = 0; mt < 4; mt++) {
        const int row  = cm + wm + mt * 16 + (lane >> 2);
        const int row2 = row + 8;
        if (MODE == 0) {
#pragma unroll
            for (int nt = 0; nt < 4; nt++) {
                const int col = cn + wn + nt * 8 + (lane & 3) * 2;
                float2 bb = *(const float2*)(bias + col);
                float2* p0 = (float2*)(out + (size_t)row  * DH + col);
                float2* p1 = (float2*)(out + (size_t)row2 * DH + col);
                float2 o0 = *p0, o1 = *p1;
                o0.x += acc[mt][nt][0] + bb.x;  o0.y += acc[mt][nt][1] + bb.y;
                o1.x += acc[mt][nt][2] + bb.x;  o1.y += acc[mt][nt][3] + bb.y;
                *p0 = o0; *p1 = o1;
            }
        } else {
            float4 v0, v1;
#pragma unroll
            for (int nt = 0; nt < 4; nt++) {
                float s0 = acc[mt][nt][0] * acc[mt][nt][0] + acc[mt][nt][1] * acc[mt][nt][1];
                float s1 = acc[mt][nt][2] * acc[mt][nt][2] + acc[mt][nt][3] * acc[mt][nt][3];
                s0 += __shfl_xor_sync(0xffffffffu, s0, 1);
                s0 += __shfl_xor_sync(0xffffffffu, s0, 2);
                s1 += __shfl_xor_sync(0xffffffffu, s1, 1);
                s1 += __shfl_xor_sync(0xffffffffu, s1, 2);
                ((float*)&v0)[nt] = 0.5f * s0;
                ((float*)&v1)[nt] = 0.5f * s1;
            }
            if ((lane & 3) == 0) {
                const int hb = (cn + wn) / 8;       // multiple of 4
                *(float4*)(out + (size_t)row  * DH + hb) = v0;
                *(float4*)(out + (size_t)row2 * DH + hb) = v1;
            }
        }
    }
}

// --------------------------------- host side --------------------------------

extern "C" void kernel_launch(void* const* d_in, const int* in_sizes, int n_in,
                              void* d_out, int out_size) {
    const float* x    = (const float*)d_in[0];
    const float* beta = (const float*)d_in[1];
    const float* W    = (const float*)d_in[2];
    const float* bias = (const float*)d_in[3];
    float* out = (float*)d_out;
    (void)in_sizes; (void)n_in; (void)out_size;

    void *pBh, *pAa, *pBa;
    cudaGetSymbolAddress(&pBh, g_Bh);
    cudaGetSymbolAddress(&pAa, g_Aa);
    cudaGetSymbolAddress(&pBa, g_Ba);

    cudaFuncSetAttribute((const void*)fm_gemm<0>,
                         cudaFuncAttributeMaxDynamicSharedMemorySize, SMEMB);
    cudaFuncSetAttribute((const void*)fm_gemm<1>,
                         cudaFuncAttributeMaxDynamicSharedMemorySize, SMEMB);

    prep_all<<<PREP_BLOCKS, 256>>>(x, beta, W);

    // main FIRST: pure stores out = 0.5 * sum_l s^2
    // A = g_Aa hi panel (KldA=1024), B = g_Bh (KldB=512), KT=8
    fm_gemm<1><<<dim3(RM / 128, DB / 128), 256, SMEMB>>>(
        (const __half*)pAa, (const __half*)pBh, out, bias, 1024, 512, 8);
    // aux second: coalesced RMW adds linear + bias - 0.5*ssq
    // A = g_Aa (KldA=1024), B = g_Ba (KldB=1024), KT=16
    fm_gemm<0><<<dim3(DH / 128, DB / 128), 256, SMEMB>>>(
        (const __half*)pAa, (const __half*)pBa, out, bias, 1024, 1024, 16);
}